// round 1
// baseline (speedup 1.0000x reference)
#include <cuda_runtime.h>
#include <cstdint>

#define BATCH 1024
#define TT 13
#define YY 188
#define HH 512
#define GG 1536   // 3*H
#define DS 13     // decode steps

// ---------------- scratch (device globals; no allocations allowed) ----------
__device__ float g_xg0[(size_t)DS * BATCH * GG];  // ring buffer of layer0 input gates
__device__ float g_gh0[(size_t)BATCH * GG];
__device__ float g_xg1[(size_t)BATCH * GG];
__device__ float g_gh1[(size_t)BATCH * GG];
__device__ float g_h0[(size_t)BATCH * HH];
__device__ float g_h1[(size_t)BATCH * HH];
__device__ float g_xlast[(size_t)BATCH * YY];

// ---------------- GEMM config ----------------
#define BM 128
#define BN 128
#define BK 32
#define NTHREADS 256
#define SMEM_BYTES (4 * BM * BK * 4)   // 2 stages A + 2 stages B = 64KB

__device__ __forceinline__ uint32_t f2tf32(float x) {
    uint32_t r;
    asm("cvt.rna.tf32.f32 %0, %1;" : "=r"(r) : "f"(x));
    return r;
}

__device__ __forceinline__ void cp16(uint32_t dst, const void* src, bool pred) {
    int sz = pred ? 16 : 0;
    asm volatile("cp.async.cg.shared.global [%0], [%1], 16, %2;\n"
                 :: "r"(dst), "l"(src), "r"(sz));
}
__device__ __forceinline__ void cp_commit() { asm volatile("cp.async.commit_group;\n"); }
__device__ __forceinline__ void cp_wait1()  { asm volatile("cp.async.wait_group 1;\n"); }

// swizzled float index inside a 128x32 tile (8 16B-vecs per row, XOR by row%8)
__device__ __forceinline__ int swz(int r, int c) {
    return r * 32 + ((((c >> 2) ^ (r & 7))) << 2) + (c & 3);
}

// MODE 0: C[r*ldc+n] = acc + bias[n]
// MODE 1: xg0_all scatter: m=(b*13+t) -> g_xg0[t][b][n], + bias
// MODE 2: out step: v=acc+bias[n]+xlast[r][n]; dout[r][dstep][n]=v; xlast[r][n]=v
template <int MODE, bool RELU_A, bool NGUARD>
__device__ __forceinline__ void gemm_core(
    const float* __restrict__ A, const float* __restrict__ Bw,
    const float* __restrict__ bias, float* __restrict__ C,
    int M, int N, int K, int lda, int ldb, int ldc,
    float* __restrict__ xlast, float* __restrict__ dout, int dstep)
{
    extern __shared__ float sm[];
    float* sA = sm;
    float* sB = sm + 2 * BM * BK;

    const int tid = threadIdx.x;
    const int lane = tid & 31;
    const int warp = tid >> 5;
    const int warpM = warp >> 1;   // 0..3 -> 32-row slices
    const int warpN = warp & 1;    // 0..1 -> 64-col slices

    const int m0 = blockIdx.y * BM;
    const int n0 = blockIdx.x * BN;

    const uint32_t sA_base = (uint32_t)__cvta_generic_to_shared(sA);
    const uint32_t sB_base = (uint32_t)__cvta_generic_to_shared(sB);

    float acc[2][8][4];
#pragma unroll
    for (int i = 0; i < 2; i++)
#pragma unroll
        for (int j = 0; j < 8; j++)
#pragma unroll
            for (int q = 0; q < 4; q++) acc[i][j][q] = 0.f;

    const int nk = (K + BK - 1) / BK;
    const int lrow = tid >> 3;  // 0..31
    const int lvc = tid & 7;    // 16B vec column

    auto load_stage = [&](int st, int k0) {
#pragma unroll
        for (int i = 0; i < 4; i++) {
            int r = lrow + i * 32;
            int kk = k0 + lvc * 4;
            bool ok = kk < K;
            int kc = ok ? kk : 0;
            const float* srcA = A + (size_t)(m0 + r) * lda + kc;
            uint32_t dA = sA_base + (uint32_t)(st * BM * BK + r * 32 + ((lvc ^ (r & 7)) << 2)) * 4u;
            cp16(dA, srcA, ok);
            int n = n0 + r;
            if (NGUARD && n >= N) n = N - 1;
            const float* srcB = Bw + (size_t)n * ldb + kc;
            uint32_t dB = sB_base + (uint32_t)(st * BM * BK + r * 32 + ((lvc ^ (r & 7)) << 2)) * 4u;
            cp16(dB, srcB, ok);
        }
    };

    load_stage(0, 0);
    cp_commit();

    int stage = 0;
    for (int kt = 0; kt < nk; kt++) {
        if (kt + 1 < nk) load_stage(stage ^ 1, (kt + 1) * BK);
        cp_commit();
        cp_wait1();
        __syncthreads();

        const float* cA = sA + stage * BM * BK;
        const float* cB = sB + stage * BM * BK;
#pragma unroll
        for (int ks = 0; ks < 4; ks++) {
            int kb = ks * 8 + (lane & 3);
            uint32_t af[2][4];
#pragma unroll
            for (int i = 0; i < 2; i++) {
                int r = warpM * 32 + i * 16 + (lane >> 2);
                float a0 = cA[swz(r, kb)];
                float a1 = cA[swz(r + 8, kb)];
                float a2 = cA[swz(r, kb + 4)];
                float a3 = cA[swz(r + 8, kb + 4)];
                if (RELU_A) {
                    a0 = fmaxf(a0, 0.f); a1 = fmaxf(a1, 0.f);
                    a2 = fmaxf(a2, 0.f); a3 = fmaxf(a3, 0.f);
                }
                af[i][0] = f2tf32(a0); af[i][1] = f2tf32(a1);
                af[i][2] = f2tf32(a2); af[i][3] = f2tf32(a3);
            }
#pragma unroll
            for (int j = 0; j < 8; j++) {
                int n = warpN * 64 + j * 8 + (lane >> 2);
                uint32_t b0 = f2tf32(cB[swz(n, kb)]);
                uint32_t b1 = f2tf32(cB[swz(n, kb + 4)]);
#pragma unroll
                for (int i = 0; i < 2; i++) {
                    asm volatile(
                        "mma.sync.aligned.m16n8k8.row.col.f32.tf32.tf32.f32 "
                        "{%0,%1,%2,%3}, {%4,%5,%6,%7}, {%8,%9}, {%0,%1,%2,%3};\n"
                        : "+f"(acc[i][j][0]), "+f"(acc[i][j][1]),
                          "+f"(acc[i][j][2]), "+f"(acc[i][j][3])
                        : "r"(af[i][0]), "r"(af[i][1]), "r"(af[i][2]), "r"(af[i][3]),
                          "r"(b0), "r"(b1));
                }
            }
        }
        __syncthreads();
        stage ^= 1;
    }

    // epilogue
#pragma unroll
    for (int i = 0; i < 2; i++) {
        int rbase = m0 + warpM * 32 + i * 16 + (lane >> 2);
#pragma unroll
        for (int j = 0; j < 8; j++) {
            int cbase = n0 + warpN * 64 + j * 8 + ((lane & 3) << 1);
#pragma unroll
            for (int q = 0; q < 4; q++) {
                int rr = rbase + (q >> 1) * 8;
                int nn = cbase + (q & 1);
                if (NGUARD && nn >= N) continue;
                float v = acc[i][j][q] + bias[nn];
                if (MODE == 0) {
                    C[(size_t)rr * ldc + nn] = v;
                } else if (MODE == 1) {
                    int b = rr / TT, t = rr % TT;
                    C[(size_t)t * (BATCH * GG) + (size_t)b * GG + nn] = v;
                } else {
                    float o = v + xlast[(size_t)rr * YY + nn];
                    dout[((size_t)rr * DS + dstep) * YY + nn] = o;
                    xlast[(size_t)rr * YY + nn] = o;
                }
            }
        }
    }
}

// ---------------- GEMM wrappers ----------------
__global__ void __launch_bounds__(NTHREADS)
k_gemm_gh0(const float* __restrict__ Whh0, const float* __restrict__ bhh0) {
    gemm_core<0, false, false>(g_h0, Whh0, bhh0, g_gh0,
                               BATCH, GG, HH, HH, HH, GG, nullptr, nullptr, 0);
}

__global__ void __launch_bounds__(NTHREADS)
k_gemm_l1(const float* __restrict__ Wih1, const float* __restrict__ bih1,
          const float* __restrict__ Whh1, const float* __restrict__ bhh1) {
    if (blockIdx.z == 0)
        gemm_core<0, false, false>(g_h0, Wih1, bih1, g_xg1,
                                   BATCH, GG, HH, HH, HH, GG, nullptr, nullptr, 0);
    else
        gemm_core<0, false, false>(g_h1, Whh1, bhh1, g_gh1,
                                   BATCH, GG, HH, HH, HH, GG, nullptr, nullptr, 0);
}

__global__ void __launch_bounds__(NTHREADS)
k_gemm_xg0_all(const float* __restrict__ x, const float* __restrict__ Wih0,
               const float* __restrict__ bih0) {
    gemm_core<1, false, false>(x, Wih0, bih0, g_xg0,
                               BATCH * TT, GG, YY, YY, YY, GG, nullptr, nullptr, 0);
}

__global__ void __launch_bounds__(NTHREADS)
k_gemm_xg0_new(const float* __restrict__ Wih0, const float* __restrict__ bih0, int slot) {
    gemm_core<0, false, false>(g_xlast, Wih0, bih0, g_xg0 + (size_t)slot * BATCH * GG,
                               BATCH, GG, YY, YY, YY, GG, nullptr, nullptr, 0);
}

__global__ void __launch_bounds__(NTHREADS)
k_gemm_out(const float* __restrict__ Wout, const float* __restrict__ bout,
           float* __restrict__ dout, int dstep) {
    gemm_core<2, true, true>(g_h1, Wout, bout, nullptr,
                             BATCH, YY, HH, HH, HH, YY, g_xlast, dout, dstep);
}

// ---------------- gate kernels ----------------
__device__ __forceinline__ float sigm(float x) { return 1.f / (1.f + __expf(-x)); }
__device__ __forceinline__ float tanh_(float x) { return 2.f * sigm(2.f * x) - 1.f; }

__global__ void k_gate0(int slot, const float* __restrict__ bhh, int bias_only) {
    int idx = blockIdx.x * blockDim.x + threadIdx.x;
    if (idx >= BATCH * HH) return;
    int b = idx >> 9, j = idx & (HH - 1);
    const float* xg = g_xg0 + (size_t)slot * BATCH * GG + (size_t)b * GG;
    float xr = xg[j], xz = xg[HH + j], xn = xg[2 * HH + j];
    float gr, gz, gn, hp;
    if (bias_only) {
        gr = bhh[j]; gz = bhh[HH + j]; gn = bhh[2 * HH + j]; hp = 0.f;
    } else {
        const float* gh = g_gh0 + (size_t)b * GG;
        gr = gh[j]; gz = gh[HH + j]; gn = gh[2 * HH + j]; hp = g_h0[idx];
    }
    float r = sigm(xr + gr), z = sigm(xz + gz);
    float n = tanh_(xn + r * gn);
    g_h0[idx] = (1.f - z) * n + z * hp;
}

__global__ void k_gate1(const float* __restrict__ bhh, int bias_only) {
    int idx = blockIdx.x * blockDim.x + threadIdx.x;
    if (idx >= BATCH * HH) return;
    int b = idx >> 9, j = idx & (HH - 1);
    const float* xg = g_xg1 + (size_t)b * GG;
    float xr = xg[j], xz = xg[HH + j], xn = xg[2 * HH + j];
    float gr, gz, gn, hp;
    if (bias_only) {
        gr = bhh[j]; gz = bhh[HH + j]; gn = bhh[2 * HH + j]; hp = 0.f;
    } else {
        const float* gh = g_gh1 + (size_t)b * GG;
        gr = gh[j]; gz = gh[HH + j]; gn = gh[2 * HH + j]; hp = g_h1[idx];
    }
    float r = sigm(xr + gr), z = sigm(xz + gz);
    float n = tanh_(xn + r * gn);
    g_h1[idx] = (1.f - z) * n + z * hp;
}

__global__ void k_init_xlast(const float* __restrict__ x) {
    int idx = blockIdx.x * blockDim.x + threadIdx.x;
    if (idx >= BATCH * YY) return;
    int b = idx / YY, y = idx % YY;
    g_xlast[idx] = x[((size_t)b * TT + (TT - 1)) * YY + y];
}

// ---------------- host driver ----------------
extern "C" void kernel_launch(void* const* d_in, const int* in_sizes, int n_in,
                              void* d_out, int out_size) {
    (void)in_sizes; (void)n_in; (void)out_size;
    const float* x    = (const float*)d_in[0];
    const float* Wih0 = (const float*)d_in[1];
    const float* Whh0 = (const float*)d_in[2];
    const float* bih0 = (const float*)d_in[3];
    const float* bhh0 = (const float*)d_in[4];
    const float* Wih1 = (const float*)d_in[5];
    const float* Whh1 = (const float*)d_in[6];
    const float* bih1 = (const float*)d_in[7];
    const float* bhh1 = (const float*)d_in[8];
    const float* Wout = (const float*)d_in[9];
    const float* bout = (const float*)d_in[10];
    float* dout = (float*)d_out;

    cudaFuncSetAttribute(k_gemm_gh0,     cudaFuncAttributeMaxDynamicSharedMemorySize, SMEM_BYTES);
    cudaFuncSetAttribute(k_gemm_l1,      cudaFuncAttributeMaxDynamicSharedMemorySize, SMEM_BYTES);
    cudaFuncSetAttribute(k_gemm_xg0_all, cudaFuncAttributeMaxDynamicSharedMemorySize, SMEM_BYTES);
    cudaFuncSetAttribute(k_gemm_xg0_new, cudaFuncAttributeMaxDynamicSharedMemorySize, SMEM_BYTES);
    cudaFuncSetAttribute(k_gemm_out,     cudaFuncAttributeMaxDynamicSharedMemorySize, SMEM_BYTES);

    dim3 blk(NTHREADS);
    dim3 gGH(GG / BN, BATCH / BM);            // 12 x 8
    dim3 gXGALL(GG / BN, BATCH * TT / BM);    // 12 x 104
    dim3 gOUT((YY + BN - 1) / BN, BATCH / BM);// 2 x 8
    int gateBlocks = (BATCH * HH + 255) / 256;
    int initBlocks = (BATCH * YY + 255) / 256;

    k_init_xlast<<<initBlocks, 256>>>(x);
    k_gemm_xg0_all<<<gXGALL, blk, SMEM_BYTES>>>(x, Wih0, bih0);

    for (int d = 0; d < DS; d++) {
        for (int t = 0; t < TT; t++) {
            int slot = (d + t) % TT;
            if (t > 0) k_gemm_gh0<<<gGH, blk, SMEM_BYTES>>>(Whh0, bhh0);
            k_gate0<<<gateBlocks, 256>>>(slot, bhh0, t == 0 ? 1 : 0);
            dim3 gl1(GG / BN, BATCH / BM, t > 0 ? 2 : 1);
            k_gemm_l1<<<gl1, blk, SMEM_BYTES>>>(Wih1, bih1, Whh1, bhh1);
            k_gate1<<<gateBlocks, 256>>>(bhh1, t == 0 ? 1 : 0);
        }
        k_gemm_out<<<gOUT, blk, SMEM_BYTES>>>(Wout, bout, dout, d);
        if (d + 1 < DS) k_gemm_xg0_new<<<gGH, blk, SMEM_BYTES>>>(Wih0, bih0, d % TT);
    }
}

// round 2
// speedup vs baseline: 1.1003x; 1.1003x over previous
#include <cuda_runtime.h>
#include <cstdint>

#define BATCH 1024
#define TT 13
#define YY 188
#define HH 512
#define GG 1536
#define DS 13
#define KPAD 192
#define NB 192     // block N tile (= 64 h-dims x 3 gates)
#define BK 32
#define NTH 256
#define SEPIL 196  // epilogue smem row stride (floats)

// ---------------- scratch ----------------
__device__ float g_xg0[(size_t)TT * BATCH * GG];   // ring: xg0 + b_ih0, permuted cols
__device__ float g_gh1[(size_t)BATCH * GG];        // h1@Whh1 + b_hh1, permuted cols
__device__ float g_h0[2][(size_t)BATCH * HH];
__device__ float g_h1[2][(size_t)BATCH * HH];
__device__ float g_xlast[(size_t)BATCH * YY];
// prepped weights: tf32-rounded, gate-permuted rows (row c <- orig row (c%3)*512 + c/3)
__device__ float g_Whh0p[(size_t)GG * HH];
__device__ float g_Wih1p[(size_t)GG * HH];
__device__ float g_Whh1p[(size_t)GG * HH];
__device__ float g_Wih0p[(size_t)GG * KPAD];       // K padded 188->192 with zeros
__device__ float g_Woutp[(size_t)KPAD * HH];       // rows >= 188 zero
__device__ float g_bih0p[GG], g_bhh0p[GG], g_bih1p[GG], g_bhh1p[GG];

// ---------------- helpers ----------------
__device__ __forceinline__ float tf32r(float x) {
    uint32_t u; asm("cvt.rna.tf32.f32 %0, %1;" : "=r"(u) : "f"(x));
    return __uint_as_float(u);
}
__device__ __forceinline__ uint32_t f2tf(float x) {
    uint32_t u; asm("cvt.rna.tf32.f32 %0, %1;" : "=r"(u) : "f"(x));
    return u;
}
__device__ __forceinline__ void cp16(uint32_t d, const void* s) {
    asm volatile("cp.async.cg.shared.global [%0], [%1], 16;\n" :: "r"(d), "l"(s));
}
__device__ __forceinline__ void cpc()  { asm volatile("cp.async.commit_group;\n"); }
__device__ __forceinline__ void cpw1() { asm volatile("cp.async.wait_group 1;\n"); }

__device__ __forceinline__ float sigm(float x)   { return 1.f / (1.f + __expf(-x)); }
__device__ __forceinline__ float tanhf_(float x) { return 2.f * sigm(2.f * x) - 1.f; }

__device__ __forceinline__ void mma8(float* d, const uint32_t* a, uint32_t b0, uint32_t b1) {
    asm volatile(
        "mma.sync.aligned.m16n8k8.row.col.f32.tf32.tf32.f32 "
        "{%0,%1,%2,%3},{%4,%5,%6,%7},{%8,%9},{%0,%1,%2,%3};\n"
        : "+f"(d[0]), "+f"(d[1]), "+f"(d[2]), "+f"(d[3])
        : "r"(a[0]), "r"(a[1]), "r"(a[2]), "r"(a[3]), "r"(b0), "r"(b1));
}

// modes
#define M_STORE 0   // C[r*GG+c] = acc + bias[c]
#define M_GATE0 1   // fused GRU layer-0 gate (gh=ring slot, bhh=bhh0p)
#define M_GATE1 2   // fused GRU layer-1 gate (acc=xg1; gh=g_gh1 or ZG->bhh1p)
#define M_XGALL 3   // scatter rows (b*13+t) into ring[t][b]
#define M_OUT   4   // relu(A) GEMM + bias + residual + dout + xlast update

// ---------------- GEMM core ----------------
template<int BM, int MODE, bool RELU_A, bool ZG>
__device__ __forceinline__ void gcore(
    const float* __restrict__ A, const float* __restrict__ Bw,
    int K, int KA, int lda, int ldb,
    float* __restrict__ C, const float* __restrict__ bias,
    const float* __restrict__ gh, const float* __restrict__ bhh,
    const float* __restrict__ hsrc, float* __restrict__ hdst,
    float* __restrict__ dout, int dstep,
    const float* __restrict__ bout, float* __restrict__ xlast)
{
    constexpr int WMC = BM / 32;          // warps along M
    constexpr int WNC = 8 / WMC;          // warps along N
    constexpr int WN  = NB / WNC;         // 96 or 48
    constexpr int J   = WN / 8;           // 12 or 6

    extern __shared__ float sm[];
    float* sA = sm;
    float* sB = sm + 3 * BM * BK;

    const int tid = threadIdx.x, lane = tid & 31, warp = tid >> 5;
    const int warpM = warp % WMC, warpN = warp / WMC;
    const int m0 = blockIdx.y * BM, n0 = blockIdx.x * NB;
    const uint32_t sAb = (uint32_t)__cvta_generic_to_shared(sA);
    const uint32_t sBb = (uint32_t)__cvta_generic_to_shared(sB);

    float acc[2][J][4];
#pragma unroll
    for (int i = 0; i < 2; i++)
#pragma unroll
        for (int j = 0; j < J; j++)
#pragma unroll
            for (int q = 0; q < 4; q++) acc[i][j][q] = 0.f;

    const int nk = K / BK;

    auto load_stage = [&](int st, int k0) {
#pragma unroll
        for (int v = tid; v < BM * 8; v += NTH) {
            int r = v >> 3, vc = v & 7, kk = k0 + vc * 4;
            const float* src = A + (size_t)(m0 + r) * lda + (kk < KA ? kk : 0);
            cp16(sAb + (uint32_t)((st * BM + r) * BK + ((vc ^ (r & 7)) << 2)) * 4u, src);
        }
#pragma unroll
        for (int v = tid; v < NB * 8; v += NTH) {
            int r = v >> 3, vc = v & 7, kk = k0 + vc * 4;
            const float* src = Bw + (size_t)(n0 + r) * ldb + kk;
            cp16(sBb + (uint32_t)((st * NB + r) * BK + ((vc ^ (r & 7)) << 2)) * 4u, src);
        }
    };

    load_stage(0, 0);  cpc();
    load_stage(1, BK); cpc();

    for (int kt = 0; kt < nk; kt++) {
        cpw1();
        __syncthreads();
        if (kt + 2 < nk) load_stage((kt + 2) % 3, (kt + 2) * BK);
        cpc();

        const int st = kt % 3;
        const float* cA = sA + st * BM * BK;
        const float* cB = sB + st * NB * BK;
#pragma unroll
        for (int ks = 0; ks < 4; ks++) {
            uint32_t af[2][4];
#pragma unroll
            for (int i = 0; i < 2; i++) {
                int r = warpM * 32 + i * 16 + (lane >> 2);
                int x7 = r & 7;                // (r+8)&7 == r&7
                int c0 = ((2 * ks) ^ x7) * 4 + (lane & 3);
                int c1 = ((2 * ks + 1) ^ x7) * 4 + (lane & 3);
                float a0 = cA[r * BK + c0];
                float a1 = cA[(r + 8) * BK + c0];
                float a2 = cA[r * BK + c1];
                float a3 = cA[(r + 8) * BK + c1];
                if (RELU_A) {
                    a0 = fmaxf(a0, 0.f); a1 = fmaxf(a1, 0.f);
                    a2 = fmaxf(a2, 0.f); a3 = fmaxf(a3, 0.f);
                }
                af[i][0] = f2tf(a0); af[i][1] = f2tf(a1);
                af[i][2] = f2tf(a2); af[i][3] = f2tf(a3);
            }
#pragma unroll
            for (int j = 0; j < J; j++) {
                int n = warpN * WN + j * 8 + (lane >> 2);
                int x7 = n & 7;
                uint32_t b0 = __float_as_uint(cB[n * BK + ((2 * ks) ^ x7) * 4 + (lane & 3)]);
                uint32_t b1 = __float_as_uint(cB[n * BK + ((2 * ks + 1) ^ x7) * 4 + (lane & 3)]);
                mma8(acc[0][j], af[0], b0, b1);
                mma8(acc[1][j], af[1], b0, b1);
            }
        }
    }

    // ---------------- epilogues ----------------
    if (MODE == M_STORE || MODE == M_XGALL) {
#pragma unroll
        for (int i = 0; i < 2; i++) {
            int rr = m0 + warpM * 32 + i * 16 + (lane >> 2);
#pragma unroll
            for (int j = 0; j < J; j++) {
                int cc = n0 + warpN * WN + j * 8 + ((lane & 3) << 1);
#pragma unroll
                for (int q = 0; q < 4; q++) {
                    int r2 = rr + (q >> 1) * 8, c2 = cc + (q & 1);
                    float v = acc[i][j][q] + bias[c2];
                    if (MODE == M_STORE) {
                        C[(size_t)r2 * GG + c2] = v;
                    } else {
                        int b = r2 / TT, t = r2 % TT;
                        C[((size_t)t * BATCH + b) * GG + c2] = v;
                    }
                }
            }
        }
    } else if (MODE == M_OUT) {
#pragma unroll
        for (int i = 0; i < 2; i++) {
            int rr = m0 + warpM * 32 + i * 16 + (lane >> 2);
#pragma unroll
            for (int j = 0; j < J; j++) {
                int cc = n0 + warpN * WN + j * 8 + ((lane & 3) << 1);
#pragma unroll
                for (int q = 0; q < 4; q++) {
                    int r2 = rr + (q >> 1) * 8, c2 = cc + (q & 1);
                    if (c2 < YY) {
                        float v = acc[i][j][q] + bout[c2];
                        float o = v + xlast[(size_t)r2 * YY + c2];
                        dout[((size_t)r2 * DS + dstep) * YY + c2] = o;
                        xlast[(size_t)r2 * YY + c2] = o;
                    }
                }
            }
        }
    } else {  // M_GATE0 / M_GATE1 : acc -> smem -> gate math
        __syncthreads();
#pragma unroll
        for (int i = 0; i < 2; i++) {
            int rl = warpM * 32 + i * 16 + (lane >> 2);
#pragma unroll
            for (int j = 0; j < J; j++) {
                int cl = warpN * WN + j * 8 + ((lane & 3) << 1);
                *(float2*)&sm[rl * SEPIL + cl]       = make_float2(acc[i][j][0], acc[i][j][1]);
                *(float2*)&sm[(rl + 8) * SEPIL + cl] = make_float2(acc[i][j][2], acc[i][j][3]);
            }
        }
        __syncthreads();
        const int jbase = n0 / 3;  // 64 * blockIdx.x
        for (int idx = tid; idx < BM * 64; idx += NTH) {
            int bl = idx >> 6, jj = idx & 63;
            int b = m0 + bl;
            int cg = n0 + 3 * jj;
            float ar = sm[bl * SEPIL + 3 * jj + 0];
            float az = sm[bl * SEPIL + 3 * jj + 1];
            float an = sm[bl * SEPIL + 3 * jj + 2];
            float xr, xz, xn, gr, gz, gn, hp;
            if (MODE == M_GATE0) {
                const float* xg = gh + (size_t)b * GG;  // ring slot (has b_ih0)
                xr = xg[cg]; xz = xg[cg + 1]; xn = xg[cg + 2];
                gr = ar + bhh[cg]; gz = az + bhh[cg + 1]; gn = an + bhh[cg + 2];
                hp = hsrc[(size_t)b * HH + jbase + jj];
            } else {
                xr = ar + bias[cg]; xz = az + bias[cg + 1]; xn = an + bias[cg + 2];
                if (ZG) {
                    gr = bhh[cg]; gz = bhh[cg + 1]; gn = bhh[cg + 2]; hp = 0.f;
                } else {
                    const float* g = gh + (size_t)b * GG;  // g_gh1 (has b_hh1)
                    gr = g[cg]; gz = g[cg + 1]; gn = g[cg + 2];
                    hp = hsrc[(size_t)b * HH + jbase + jj];
                }
            }
            float r = sigm(xr + gr), z = sigm(xz + gz);
            float nn_ = tanhf_(xn + r * gn);
            hdst[(size_t)b * HH + jbase + jj] = (1.f - z) * nn_ + z * hp;
        }
    }
}

// ---------------- kernels ----------------
__global__ void __launch_bounds__(NTH, 1) k_rec(int par, int slot) {
    const float* ring = g_xg0 + (size_t)slot * BATCH * GG;
    if (blockIdx.z == 0)
        gcore<128, M_GATE0, false, false>(g_h0[par ^ 1], g_Whh0p, HH, HH, HH, HH,
            nullptr, nullptr, ring, g_bhh0p, g_h0[par ^ 1], g_h0[par],
            nullptr, 0, nullptr, nullptr);
    else
        gcore<128, M_STORE, false, false>(g_h1[par ^ 1], g_Whh1p, HH, HH, HH, HH,
            g_gh1, g_bhh1p, nullptr, nullptr, nullptr, nullptr,
            nullptr, 0, nullptr, nullptr);
}

template<bool ZG>
__global__ void __launch_bounds__(NTH, 1) k_xg1(int par) {
    gcore<64, M_GATE1, false, ZG>(g_h0[par], g_Wih1p, HH, HH, HH, HH,
        nullptr, g_bih1p, g_gh1, g_bhh1p, g_h1[par ^ 1], g_h1[par],
        nullptr, 0, nullptr, nullptr);
}

__global__ void __launch_bounds__(NTH, 1) k_xg0_all(const float* __restrict__ x) {
    gcore<128, M_XGALL, false, false>(x, g_Wih0p, KPAD, YY, YY, KPAD,
        g_xg0, g_bih0p, nullptr, nullptr, nullptr, nullptr,
        nullptr, 0, nullptr, nullptr);
}

__global__ void __launch_bounds__(NTH, 1) k_xg0_new(int slot) {
    gcore<64, M_STORE, false, false>(g_xlast, g_Wih0p, KPAD, YY, YY, KPAD,
        g_xg0 + (size_t)slot * BATCH * GG, g_bih0p, nullptr, nullptr, nullptr, nullptr,
        nullptr, 0, nullptr, nullptr);
}

__global__ void __launch_bounds__(NTH, 1) k_out(float* __restrict__ dout, int dstep,
                                                const float* __restrict__ bout) {
    gcore<64, M_OUT, true, false>(g_h1[0], g_Woutp, HH, HH, HH, HH,
        nullptr, nullptr, nullptr, nullptr, nullptr, nullptr,
        dout, dstep, bout, g_xlast);
}

__global__ void k_gate0_init(int slot) {
    int idx = blockIdx.x * blockDim.x + threadIdx.x;
    if (idx >= BATCH * HH) return;
    int b = idx >> 9;
    int j = idx & 511;
    const float* xg = g_xg0 + (size_t)slot * BATCH * GG + (size_t)b * GG;
    int c = 3 * j;
    float r = sigm(xg[c] + g_bhh0p[c]);
    float z = sigm(xg[c + 1] + g_bhh0p[c + 1]);
    float n = tanhf_(xg[c + 2] + r * g_bhh0p[c + 2]);
    g_h0[0][idx] = (1.f - z) * n;
}

__global__ void k_init_xlast(const float* __restrict__ x) {
    int idx = blockIdx.x * blockDim.x + threadIdx.x;
    if (idx >= BATCH * YY) return;
    int b = idx / YY, y = idx % YY;
    g_xlast[idx] = x[((size_t)b * TT + (TT - 1)) * YY + y];
}

__global__ void k_prep(const float* __restrict__ Wih0, const float* __restrict__ Whh0,
                       const float* __restrict__ bih0, const float* __restrict__ bhh0,
                       const float* __restrict__ Wih1, const float* __restrict__ Whh1,
                       const float* __restrict__ bih1, const float* __restrict__ bhh1,
                       const float* __restrict__ Wout) {
    int i = blockIdx.x * blockDim.x + threadIdx.x;
    if (i < GG * HH) {
        int c = i / HH, k = i % HH;
        int pr = (c % 3) * HH + c / 3;
        g_Whh0p[i] = tf32r(Whh0[(size_t)pr * HH + k]);
        g_Wih1p[i] = tf32r(Wih1[(size_t)pr * HH + k]);
        g_Whh1p[i] = tf32r(Whh1[(size_t)pr * HH + k]);
    }
    if (i < GG * KPAD) {
        int c = i / KPAD, k = i % KPAD;
        int pr = (c % 3) * HH + c / 3;
        g_Wih0p[i] = (k < YY) ? tf32r(Wih0[(size_t)pr * YY + k]) : 0.f;
    }
    if (i < KPAD * HH) {
        int r = i / HH, k = i % HH;
        g_Woutp[i] = (r < YY) ? tf32r(Wout[(size_t)r * HH + k]) : 0.f;
    }
    if (i < GG) {
        int pr = (i % 3) * HH + i / 3;
        g_bih0p[i] = bih0[pr];
        g_bhh0p[i] = bhh0[pr];
        g_bih1p[i] = bih1[pr];
        g_bhh1p[i] = bhh1[pr];
    }
}

// ---------------- host ----------------
#define SM128 (3 * (128 + NB) * BK * 4)   // 122880 B
#define SM64  (3 * (64 + NB) * BK * 4)    //  98304 B

extern "C" void kernel_launch(void* const* d_in, const int* in_sizes, int n_in,
                              void* d_out, int out_size) {
    (void)in_sizes; (void)n_in; (void)out_size;
    const float* x    = (const float*)d_in[0];
    const float* Wih0 = (const float*)d_in[1];
    const float* Whh0 = (const float*)d_in[2];
    const float* bih0 = (const float*)d_in[3];
    const float* bhh0 = (const float*)d_in[4];
    const float* Wih1 = (const float*)d_in[5];
    const float* Whh1 = (const float*)d_in[6];
    const float* bih1 = (const float*)d_in[7];
    const float* bhh1 = (const float*)d_in[8];
    const float* Wout = (const float*)d_in[9];
    const float* bout = (const float*)d_in[10];
    float* dout = (float*)d_out;

    cudaFuncSetAttribute(k_rec,        cudaFuncAttributeMaxDynamicSharedMemorySize, SM128);
    cudaFuncSetAttribute(k_xg0_all,    cudaFuncAttributeMaxDynamicSharedMemorySize, SM128);
    cudaFuncSetAttribute(k_xg1<true>,  cudaFuncAttributeMaxDynamicSharedMemorySize, SM64);
    cudaFuncSetAttribute(k_xg1<false>, cudaFuncAttributeMaxDynamicSharedMemorySize, SM64);
    cudaFuncSetAttribute(k_xg0_new,    cudaFuncAttributeMaxDynamicSharedMemorySize, SM64);
    cudaFuncSetAttribute(k_out,        cudaFuncAttributeMaxDynamicSharedMemorySize, SM64);

    k_prep<<<(GG * HH + 255) / 256, 256>>>(Wih0, Whh0, bih0, bhh0,
                                           Wih1, Whh1, bih1, bhh1, Wout);
    k_init_xlast<<<(BATCH * YY + 255) / 256, 256>>>(x);
    k_xg0_all<<<dim3(GG / NB, BATCH * TT / 128), NTH, SM128>>>(x);

    for (int d = 0; d < DS; d++) {
        // t = 0: h_prev = 0 fast paths
        k_gate0_init<<<(BATCH * HH + 255) / 256, 256>>>(d % TT);
        k_xg1<true><<<dim3(GG / NB, BATCH / 64), NTH, SM64>>>(0);
        for (int t = 1; t < TT; t++) {
            k_rec<<<dim3(GG / NB, BATCH / 128, 2), NTH, SM128>>>(t & 1, (d + t) % TT);
            k_xg1<false><<<dim3(GG / NB, BATCH / 64), NTH, SM64>>>(t & 1);
        }
        k_out<<<dim3(1, BATCH / 64), NTH, SM64>>>(dout, d, bout);  // h1 parity of t=12 is 0
        if (d + 1 < DS) k_xg0_new<<<dim3(GG / NB, BATCH / 64), NTH, SM64>>>(d % TT);
    }
}